// round 12
// baseline (speedup 1.0000x reference)
#include <cuda_runtime.h>

typedef unsigned long long ull;

__device__ __forceinline__ ull ffma2(ull a, ull b, ull c) {
    ull d; asm("fma.rn.f32x2 %0, %1, %2, %3;" : "=l"(d) : "l"(a), "l"(b), "l"(c)); return d;
}
__device__ __forceinline__ ull fadd2(ull a, ull b) {
    ull d; asm("add.rn.f32x2 %0, %1, %2;" : "=l"(d) : "l"(a), "l"(b)); return d;
}
__device__ __forceinline__ ull fpack(float lo, float hi) {
    ull d; asm("mov.b64 %0, {%1, %2};" : "=l"(d) : "f"(lo), "f"(hi)); return d;
}
__device__ __forceinline__ void funpack(ull v, float& lo, float& hi) {
    asm("mov.b64 {%0, %1}, %2;" : "=f"(lo), "=f"(hi) : "l"(v));
}

namespace {
constexpr int D  = 256;
constexpr int H  = 8;
constexpr int HD = 32;
constexpr int S  = 255;
constexpr int S1 = 256;
constexpr int B  = 4;
constexpr int AOFF = B * S1 * H * HD;
constexpr int ITILE = 4;
constexpr int STILE = 8;
}

// ---------------- device scratch ----------------
__device__ float2 g_vWT2 [(D/2) * D];
__device__ float2 g_W1Ta2[(D/2) * D];
__device__ float2 g_W1Tb2[(D/2) * D];
__device__ float  g_uk[H * D];
__device__ float  g_V2[D * H];
__device__ float  g_A[B * S1 * D];
__device__ float  g_Brow[B * S1 * D];
__device__ float2 g_At2[B * (D/2) * S1];
__device__ float2 g_Bt2[B * (D/2) * S1];
__device__ float  g_v[B * S1 * D];
__device__ float  g_ks[B * H * S1];
__device__ float  g_SA[B * S1];
__device__ float  g_QA[B * S1];
__device__ float  g_SB[B * S1];
__device__ float  g_QB[B * S1];
__device__ float  g_G0[B * S1 * S1];
__device__ float  g_G1[B * S1 * S1];
__device__ float  g_part0[B * S1 * H * S1];
__device__ float  g_part1[B * S1 * H * S1];

// ---------------- kernel 0a: coalesced transpose -> paired layout ----------------
__global__ void k_transpose(const float* __restrict__ vW, const float* __restrict__ eW1) {
    int which = blockIdx.z;
    int c0 = blockIdx.y * 32, k20 = blockIdx.x * 32;
    __shared__ float2 tile[32][33];
    int lx = threadIdx.x & 31;
    int ly = threadIdx.x >> 5;

#pragma unroll
    for (int cc = ly; cc < 32; cc += 8) {
        int c = c0 + cc, k = (k20 + lx) * 2;
        const float* p = (which == 0) ? vW + c * D + k
                       : (which == 1) ? eW1 + c * 2 * D + k
                                      : eW1 + c * 2 * D + D + k;
        tile[cc][lx] = *(const float2*)p;
    }
    __syncthreads();
    float2* dst = (which == 0) ? g_vWT2 : (which == 1) ? g_W1Ta2 : g_W1Tb2;
#pragma unroll
    for (int cc = ly; cc < 32; cc += 8) {
        int k2 = k20 + cc, c = c0 + lx;
        dst[k2 * D + c] = tile[lx][cc];
    }
}

// ---------------- kernel 0b: fold attention vectors ----------------
__global__ void k_wvec(const float* __restrict__ kW, const float* __restrict__ eW2,
                       const float* __restrict__ aW) {
    int h = blockIdx.x, c = threadIdx.x;
    float ak = 0.f, av = 0.f;
#pragma unroll
    for (int d = 0; d < HD; d++) {
        ak = fmaf(aW[HD + d],     kW [(h * HD + d) * D + c], ak);
        av = fmaf(aW[2 * HD + d], eW2[(h * HD + d) * D + c], av);
    }
    g_uk[h * D + c] = ak;
    g_V2[c * H + h] = av;
}

// ---------------- kernel 1: per-node precompute (f32x2) ----------------
__global__ void __launch_bounds__(256) k_node(
    const float* __restrict__ desc, const float* __restrict__ nve,
    const float* __restrict__ vb,   const float* __restrict__ eb1) {
    int b = blockIdx.x >> 5, s0 = (blockIdx.x & 31) * STILE, c = threadIdx.x;
    __shared__ float nv[STILE][D];
    __shared__ float ds[STILE][D];
    __shared__ float4 wr[8];

#pragma unroll
    for (int r = 0; r < STILE; r++) {
        nv[r][c] = nve[(b * S1 + s0 + r) * D + c];
        ds[r][c] = (s0 + r < S) ? desc[(b * S + s0 + r) * D + c] : 0.f;
    }
    __syncthreads();

    ull accv2[STILE], acca2[STILE], accb2[STILE];
    float vbc = vb[c], eb1c = eb1[c];
#pragma unroll
    for (int r = 0; r < STILE; r++) {
        accv2[r] = fpack(vbc, 0.f);
        acca2[r] = fpack(0.f, 0.f);
        accb2[r] = fpack(eb1c, 0.f);
    }

#pragma unroll 4
    for (int k2 = 0; k2 < D / 2; k2++) {
        float2 w0 = g_vWT2 [k2 * D + c];
        float2 w1 = g_W1Ta2[k2 * D + c];
        float2 w2 = g_W1Tb2[k2 * D + c];
        ull w0u = *(ull*)&w0, w1u = *(ull*)&w1, w2u = *(ull*)&w2;
#pragma unroll
        for (int r = 0; r < STILE; r++) {
            ull nvp = *(const ull*)&nv[r][2 * k2];
            ull dsp = *(const ull*)&ds[r][2 * k2];
            accv2[r] = ffma2(nvp, w0u, accv2[r]);
            acca2[r] = ffma2(dsp, w1u, acca2[r]);
            accb2[r] = ffma2(dsp, w2u, accb2[r]);
        }
    }

    float accv[STILE], acca[STILE], accb[STILE];
#pragma unroll
    for (int r = 0; r < STILE; r++) {
        float lo, hi;
        funpack(accv2[r], lo, hi); accv[r] = lo + hi;
        funpack(acca2[r], lo, hi); acca[r] = lo + hi;
        funpack(accb2[r], lo, hi); accb[r] = lo + hi;
    }

    int lane = c & 31, w = c >> 5;
#pragma unroll
    for (int r = 0; r < STILE; r++) {
        int s = s0 + r;
        bool valid = (s < S);
        float a  = valid ? acca[r] : 0.f;
        float bb = valid ? accb[r] : 0.f;
        g_v   [(b * S1 + s) * D + c] = accv[r];
        g_A   [(b * S1 + s) * D + c] = a;
        g_Brow[(b * S1 + s) * D + c] = bb;
        ((float*)g_At2)[((b * 128 + (c >> 1)) * S1 + s) * 2 + (c & 1)] = a;
        ((float*)g_Bt2)[((b * 128 + (c >> 1)) * S1 + s) * 2 + (c & 1)] = bb;

        float4 v4 = make_float4(a, a * a, bb, bb * bb);
#pragma unroll
        for (int o = 16; o > 0; o >>= 1) {
            v4.x += __shfl_xor_sync(0xffffffffu, v4.x, o);
            v4.y += __shfl_xor_sync(0xffffffffu, v4.y, o);
            v4.z += __shfl_xor_sync(0xffffffffu, v4.z, o);
            v4.w += __shfl_xor_sync(0xffffffffu, v4.w, o);
        }
        if (lane == 0) wr[w] = v4;
        __syncthreads();
        if (c == 0) {
            float4 t = wr[0];
#pragma unroll
            for (int q = 1; q < 8; q++) {
                float4 o = wr[q];
                t.x += o.x; t.y += o.y; t.z += o.z; t.w += o.w;
            }
            g_SA[b * S1 + s] = t.x; g_QA[b * S1 + s] = t.y;
            g_SB[b * S1 + s] = t.z; g_QB[b * S1 + s] = t.w;
        }
        __syncthreads();
    }

    {
        float kacc[H];
#pragma unroll
        for (int h = 0; h < H; h++) kacc[h] = 0.f;
        for (int k = lane; k < D; k += 32) {
            float n = nv[w][k];
#pragma unroll
            for (int h = 0; h < H; h++) kacc[h] = fmaf(n, g_uk[h * D + k], kacc[h]);
        }
#pragma unroll
        for (int h = 0; h < H; h++) {
#pragma unroll
            for (int o = 16; o > 0; o >>= 1)
                kacc[h] += __shfl_xor_sync(0xffffffffu, kacc[h], o);
            if (lane == 0) g_ks[(b * H + h) * S1 + s0 + w] = kacc[h];
        }
    }
}

// ---------------- kernel 1b: G partials; K=128 slab, f32x2 dot, conflict-free B ----------------
__global__ void __launch_bounds__(256) k_gemmG() {
    int kh = blockIdx.z & 1;
    int b  = blockIdx.z >> 1;
    int i0 = blockIdx.y * 32;
    int j0 = blockIdx.x * 32;
    __shared__ float As[32][132];   // [i][k], pad 132 (row base 16B-aligned)
    __shared__ float Bs[32][132];   // [j][k]
    int t = threadIdx.x;
    int lrow = t >> 3, lc = (t & 7) * 4;
    int kbeg = kh * 128;

#pragma unroll
    for (int ph = 0; ph < 4; ph++) {
        *(float4*)&As[lrow][lc + ph * 32] =
            *(const float4*)&g_A   [(b * S1 + i0 + lrow) * D + kbeg + lc + ph * 32];
        *(float4*)&Bs[lrow][lc + ph * 32] =
            *(const float4*)&g_Brow[(b * S1 + j0 + lrow) * D + kbeg + lc + ph * 32];
    }
    __syncthreads();

    int j  = (t & 7) | ((t >> 6) << 3);   // 8 consecutive j per warp -> conflict-free LDS.128
    int ig = (t >> 3) & 7;                // 4 consecutive ig per warp

    ull acc2[4];
    ull z = fpack(0.f, 0.f);
#pragma unroll
    for (int m = 0; m < 4; m++) acc2[m] = z;

#pragma unroll 4
    for (int kk = 0; kk < 128; kk += 4) {
        ulonglong2 bb = *(const ulonglong2*)&Bs[j][kk];
#pragma unroll
        for (int m = 0; m < 4; m++) {
            ulonglong2 aa = *(const ulonglong2*)&As[ig * 4 + m][kk];
            acc2[m] = ffma2(aa.x, bb.x, acc2[m]);
            acc2[m] = ffma2(aa.y, bb.y, acc2[m]);
        }
    }
    float* dst = kh ? g_G1 : g_G0;
#pragma unroll
    for (int m = 0; m < 4; m++) {
        float lo, hi; funpack(acc2[m], lo, hi);
        dst[(b * S1 + i0 + ig * 4 + m) * S1 + j0 + j] = lo + hi;
    }
}

// ---------------- kernel 2a: partial logits (channel-split) ----------------
template <bool CLS>
__device__ __forceinline__ void edge_loop(
    int base, const long long* __restrict__ btp, const long long* __restrict__ atp,
    const float (*As4)[D], const ull* gp2, const ull* bp2,
    const ulonglong2* V2u, const ull* rstd2, const ull* nmu2,
    ull acc01[ITILE], ull acc23[ITILE], ull acc45[ITILE], ull acc67[ITILE]) {
#pragma unroll 2
    for (int cc = 0; cc < 64; cc++) {
        int c2 = base + cc;
        ull bt2 = (ull)btp[c2 * S1];
        ull acls = 0;
        if (CLS) acls = (ull)atp[c2 * S1];
        ull g2 = gp2[c2], b2 = bp2[c2];
        ulonglong2 p0 = V2u[4 * c2 + 0], p1 = V2u[4 * c2 + 1];
        ulonglong2 p2 = V2u[4 * c2 + 2], p3 = V2u[4 * c2 + 3];
#pragma unroll
        for (int r = 0; r < ITILE; r++) {
            ull a2 = (CLS && r == 0) ? acls : *(const ull*)&As4[r][2 * c2];
            ull x2 = fadd2(a2, bt2);
            ull t2 = ffma2(x2, rstd2[r], nmu2[r]);
            ull y2 = ffma2(t2, g2, b2);
            float y0, y1; funpack(y2, y0, y1);
            y0 = fmaxf(y0, 0.f); y1 = fmaxf(y1, 0.f);
            ull yy0 = fpack(y0, y0), yy1 = fpack(y1, y1);
            acc01[r] = ffma2(yy0, p0.x, acc01[r]);
            acc23[r] = ffma2(yy0, p0.y, acc23[r]);
            acc45[r] = ffma2(yy0, p1.x, acc45[r]);
            acc67[r] = ffma2(yy0, p1.y, acc67[r]);
            acc01[r] = ffma2(yy1, p2.x, acc01[r]);
            acc23[r] = ffma2(yy1, p2.y, acc23[r]);
            acc45[r] = ffma2(yy1, p3.x, acc45[r]);
            acc67[r] = ffma2(yy1, p3.y, acc67[r]);
        }
    }
}

__global__ void __launch_bounds__(256) k_logits(
    const float* __restrict__ lng, const float* __restrict__ lnb) {
    int i0 = blockIdx.x * ITILE;
    int b  = blockIdx.y;
    int half = blockIdx.z;
    int t = threadIdx.x;
    bool hasCls = (i0 == 0);

    __shared__ float As4[ITILE][D];
    __shared__ ull gp2[D / 2];
    __shared__ ull bp2[D / 2];
    __shared__ ulonglong2 V2u[2 * D];

#pragma unroll
    for (int r = 0; r < ITILE; r++) {
        int i = i0 + r;
        As4[r][t] = (i > 0) ? g_A[(b * S1 + i - 1) * D + t] : 0.f;
    }
    if (t < 128) {
        gp2[t] = fpack(lng[2 * t], lng[2 * t + 1]);
        bp2[t] = fpack(lnb[2 * t], lnb[2 * t + 1]);
    }
    {
        const ulonglong2* src = (const ulonglong2*)g_V2;
        V2u[t] = src[t]; V2u[t + 256] = src[t + 256];
    }
    __syncthreads();

    int jn = (t > 0) ? t - 1 : 0;
    float sb = g_SB[b * S1 + jn], qb = g_QB[b * S1 + jn];
    ull rstd2[ITILE], nmu2[ITILE];
#pragma unroll
    for (int r = 0; r < ITILE; r++) {
        int i = i0 + r;
        float sa, qa, gij;
        if (i == 0) {
            sa = g_SA[b * S1 + jn]; qa = g_QA[b * S1 + jn];
            gij = g_G0[(b * S1 + jn) * S1 + jn] + g_G1[(b * S1 + jn) * S1 + jn];
        } else {
            sa = g_SA[b * S1 + i - 1]; qa = g_QA[b * S1 + i - 1];
            gij = g_G0[(b * S1 + i - 1) * S1 + jn] + g_G1[(b * S1 + i - 1) * S1 + jn];
        }
        const float invD = 1.0f / D;
        float m = (sa + sb) * invD;
        float var = fmaf(2.f, gij, qa + qb) * invD - m * m;
        float rs = rsqrtf(var + 1e-5f);
        rstd2[r] = fpack(rs, rs);
        float nm = -m * rs;
        nmu2[r] = fpack(nm, nm);
    }

    const long long* btp = (const long long*)g_Bt2 + (long long)(b * 128) * S1 + jn;
    const long long* atp = (const long long*)g_At2 + (long long)(b * 128) * S1 + jn;

    ull acc01[ITILE], acc23[ITILE], acc45[ITILE], acc67[ITILE];
    ull z = fpack(0.f, 0.f);
#pragma unroll
    for (int r = 0; r < ITILE; r++) { acc01[r] = z; acc23[r] = z; acc45[r] = z; acc67[r] = z; }

    int base = half * 64;
    if (hasCls) edge_loop<true >(base, btp, atp, As4, gp2, bp2, V2u, rstd2, nmu2, acc01, acc23, acc45, acc67);
    else        edge_loop<false>(base, btp, atp, As4, gp2, bp2, V2u, rstd2, nmu2, acc01, acc23, acc45, acc67);

    float* dst = half ? g_part1 : g_part0;
#pragma unroll
    for (int r = 0; r < ITILE; r++) {
        float l0, l1, l2, l3, l4, l5, l6, l7;
        funpack(acc01[r], l0, l1); funpack(acc23[r], l2, l3);
        funpack(acc45[r], l4, l5); funpack(acc67[r], l6, l7);
        float hv[H] = {l0, l1, l2, l3, l4, l5, l6, l7};
        float* pp = dst + ((b * S1 + i0 + r) * H) * S1 + t;
#pragma unroll
        for (int h = 0; h < H; h++) pp[h * S1] = hv[h];
    }
}

// ---------------- kernel 2b: softmax + attn write (no ctx) ----------------
__global__ void __launch_bounds__(256) k_smax(float* __restrict__ out) {
    int b = blockIdx.x >> 8, i = blockIdx.x & 255;
    int t = threadIdx.x;
    __shared__ float attn_s[H][S1];
    __shared__ float red[H];

    const float* p0 = g_part0 + ((b * S1 + i) * H) * S1 + t;
    const float* p1 = g_part1 + ((b * S1 + i) * H) * S1 + t;
    const float* ksp = g_ks + b * H * S1 + t;

    float lg[H];
#pragma unroll
    for (int h = 0; h < H; h++) {
        lg[h] = (t > 0) ? p0[h * S1] + p1[h * S1] + ksp[h * S1] : -1e30f;
        attn_s[h][t] = lg[h];
    }
    __syncthreads();

    int w = t >> 5, l = t & 31;
    float m = -1e30f;
#pragma unroll
    for (int k = 0; k < 8; k++) m = fmaxf(m, attn_s[w][l + 32 * k]);
#pragma unroll
    for (int o = 16; o > 0; o >>= 1) m = fmaxf(m, __shfl_xor_sync(0xffffffffu, m, o));
    if (l == 0) red[w] = m;
    __syncthreads();

    float p[H];
#pragma unroll
    for (int h = 0; h < H; h++) {
        p[h] = (t > 0) ? __expf(lg[h] - red[h]) : 0.f;
        attn_s[h][t] = p[h];
    }
    __syncthreads();

    float sm = 0.f;
#pragma unroll
    for (int k = 0; k < 8; k++) sm += attn_s[w][l + 32 * k];
#pragma unroll
    for (int o = 16; o > 0; o >>= 1) sm += __shfl_xor_sync(0xffffffffu, sm, o);
    if (l == 0) red[w] = 1.0f / sm;
    __syncthreads();

    float* arow = out + AOFF + ((b * H) * S1 + i) * S1 + t;
#pragma unroll
    for (int h = 0; h < H; h++)
        arow[h * S1 * S1] = p[h] * red[h];
}

// ---------------- kernel 2c: ctx = attn @ v as tiled GEMM ----------------
// tile: 32 i x 64 d (2 heads); K = 256 j in 4 chunks of 64
__global__ void __launch_bounds__(256) k_ctx(float* __restrict__ out) {
    int i0 = blockIdx.x * 32;
    int hp = blockIdx.y;   // head pair
    int b  = blockIdx.z;
    int t = threadIdx.x;
    __shared__ float at_s[2][32][68];
    __shared__ float v_s[64][68];

    int d2 = t & 31, ig = t >> 5;
    int hh = d2 >> 4;
    int lrow = t >> 2, lq = (t & 3) * 16;
    int hh_l = lrow >> 5, i_l = lrow & 31;

    const float* attn_src = out + AOFF;

    float acc[4][2];
#pragma unroll
    for (int m = 0; m < 4; m++) { acc[m][0] = 0.f; acc[m][1] = 0.f; }

    for (int jc = 0; jc < 4; jc++) {
        const float* asrc = attn_src +
            ((size_t)((b * H + hp * 2 + hh_l) * S1 + i0 + i_l)) * S1 + jc * 64 + lq;
        const float* vsrc = g_v + ((size_t)(b * S1) + jc * 64 + lrow) * D + hp * 64 + lq;
#pragma unroll
        for (int q = 0; q < 4; q++) {
            *(float4*)&at_s[hh_l][i_l][lq + q * 4] = *(const float4*)(asrc + q * 4);
            *(float4*)&v_s[lrow][lq + q * 4]       = *(const float4*)(vsrc + q * 4);
        }
        __syncthreads();
#pragma unroll 4
        for (int jj = 0; jj < 64; jj++) {
            float2 vv = *(const float2*)&v_s[jj][2 * d2];
#pragma unroll
            for (int m = 0; m < 4; m++) {
                float a = at_s[hh][ig * 4 + m][jj];
                acc[m][0] = fmaf(a, vv.x, acc[m][0]);
                acc[m][1] = fmaf(a, vv.y, acc[m][1]);
            }
        }
        __syncthreads();
    }
#pragma unroll
    for (int m = 0; m < 4; m++) {
        float2 r = make_float2(acc[m][0], acc[m][1]);
        *(float2*)&out[((size_t)(b * S1) + i0 + ig * 4 + m) * D + hp * 64 + 2 * d2] = r;
    }
}

// ---------------- launch ----------------
extern "C" void kernel_launch(void* const* d_in, const int* in_sizes, int n_in,
                              void* d_out, int out_size) {
    (void)in_sizes; (void)n_in; (void)out_size;
    const float* desc = (const float*)d_in[0];
    const float* nve  = (const float*)d_in[1];
    const float* kW   = (const float*)d_in[4];
    const float* vW   = (const float*)d_in[6];
    const float* vb   = (const float*)d_in[7];
    const float* eW1  = (const float*)d_in[8];
    const float* eb1  = (const float*)d_in[9];
    const float* lng  = (const float*)d_in[10];
    const float* lnb  = (const float*)d_in[11];
    const float* eW2  = (const float*)d_in[12];
    const float* aW   = (const float*)d_in[14];
    float* out = (float*)d_out;

    k_transpose<<<dim3(4, 8, 3), 256>>>(vW, eW1);
    k_wvec<<<H, 256>>>(kW, eW2, aW);
    k_node<<<B * 32, 256>>>(desc, nve, vb, eb1);
    k_gemmG<<<dim3(8, 8, B * 2), 256>>>();
    k_logits<<<dim3(S1 / ITILE, B, 2), 256>>>(lng, lnb);
    k_smax<<<B * S1, 256>>>(out);
    k_ctx<<<dim3(8, 4, B), 256>>>(out);
}

// round 14
// speedup vs baseline: 1.0794x; 1.0794x over previous
#include <cuda_runtime.h>
#include <cuda_bf16.h>
#include <mma.h>

using namespace nvcuda;

typedef unsigned long long ull;

__device__ __forceinline__ ull ffma2(ull a, ull b, ull c) {
    ull d; asm("fma.rn.f32x2 %0, %1, %2, %3;" : "=l"(d) : "l"(a), "l"(b), "l"(c)); return d;
}
__device__ __forceinline__ ull fadd2(ull a, ull b) {
    ull d; asm("add.rn.f32x2 %0, %1, %2;" : "=l"(d) : "l"(a), "l"(b)); return d;
}
__device__ __forceinline__ ull fpack(float lo, float hi) {
    ull d; asm("mov.b64 %0, {%1, %2};" : "=l"(d) : "f"(lo), "f"(hi)); return d;
}
__device__ __forceinline__ void funpack(ull v, float& lo, float& hi) {
    asm("mov.b64 {%0, %1}, %2;" : "=f"(lo), "=f"(hi) : "l"(v));
}

namespace {
constexpr int D  = 256;
constexpr int H  = 8;
constexpr int HD = 32;
constexpr int S  = 255;
constexpr int S1 = 256;
constexpr int B  = 4;
constexpr int AOFF = B * S1 * H * HD;
constexpr int ITILE = 4;
constexpr int STILE = 8;
}

// ---------------- device scratch ----------------
__device__ float2 g_vWT2 [(D/2) * D];
__device__ float2 g_W1Ta2[(D/2) * D];
__device__ float2 g_W1Tb2[(D/2) * D];
__device__ float  g_uk[H * D];
__device__ float  g_V2[D * H];
__device__ float  g_A[B * S1 * D];
__device__ float  g_Brow[B * S1 * D];
__device__ __align__(16) __nv_bfloat16 g_Abf[B * S1 * D];
__device__ __align__(16) __nv_bfloat16 g_Bbf[B * S1 * D];
__device__ float2 g_At2[B * (D/2) * S1];
__device__ float2 g_Bt2[B * (D/2) * S1];
__device__ float  g_v[B * S1 * D];
__device__ float  g_ks[B * H * S1];
__device__ float  g_SA[B * S1];
__device__ float  g_QA[B * S1];
__device__ float  g_SB[B * S1];
__device__ float  g_QB[B * S1];
__device__ float  g_G[B * S1 * S1];
__device__ float  g_part0[B * S1 * H * S1];
__device__ float  g_part1[B * S1 * H * S1];

// ---------------- kernel 0a: coalesced transpose -> paired layout ----------------
__global__ void k_transpose(const float* __restrict__ vW, const float* __restrict__ eW1) {
    int which = blockIdx.z;
    int c0 = blockIdx.y * 32, k20 = blockIdx.x * 32;
    __shared__ float2 tile[32][33];
    int lx = threadIdx.x & 31;
    int ly = threadIdx.x >> 5;

#pragma unroll
    for (int cc = ly; cc < 32; cc += 8) {
        int c = c0 + cc, k = (k20 + lx) * 2;
        const float* p = (which == 0) ? vW + c * D + k
                       : (which == 1) ? eW1 + c * 2 * D + k
                                      : eW1 + c * 2 * D + D + k;
        tile[cc][lx] = *(const float2*)p;
    }
    __syncthreads();
    float2* dst = (which == 0) ? g_vWT2 : (which == 1) ? g_W1Ta2 : g_W1Tb2;
#pragma unroll
    for (int cc = ly; cc < 32; cc += 8) {
        int k2 = k20 + cc, c = c0 + lx;
        dst[k2 * D + c] = tile[lx][cc];
    }
}

// ---------------- kernel 0b: fold attention vectors ----------------
__global__ void k_wvec(const float* __restrict__ kW, const float* __restrict__ eW2,
                       const float* __restrict__ aW) {
    int h = blockIdx.x, c = threadIdx.x;
    float ak = 0.f, av = 0.f;
#pragma unroll
    for (int d = 0; d < HD; d++) {
        ak = fmaf(aW[HD + d],     kW [(h * HD + d) * D + c], ak);
        av = fmaf(aW[2 * HD + d], eW2[(h * HD + d) * D + c], av);
    }
    g_uk[h * D + c] = ak;
    g_V2[c * H + h] = av;
}

// ---------------- kernel 1: per-node precompute (f32x2) ----------------
__global__ void __launch_bounds__(256) k_node(
    const float* __restrict__ desc, const float* __restrict__ nve,
    const float* __restrict__ vb,   const float* __restrict__ eb1) {
    int b = blockIdx.x >> 5, s0 = (blockIdx.x & 31) * STILE, c = threadIdx.x;
    __shared__ float nv[STILE][D];
    __shared__ float ds[STILE][D];
    __shared__ float4 wr[8];

#pragma unroll
    for (int r = 0; r < STILE; r++) {
        nv[r][c] = nve[(b * S1 + s0 + r) * D + c];
        ds[r][c] = (s0 + r < S) ? desc[(b * S + s0 + r) * D + c] : 0.f;
    }
    __syncthreads();

    ull accv2[STILE], acca2[STILE], accb2[STILE];
    float vbc = vb[c], eb1c = eb1[c];
#pragma unroll
    for (int r = 0; r < STILE; r++) {
        accv2[r] = fpack(vbc, 0.f);
        acca2[r] = fpack(0.f, 0.f);
        accb2[r] = fpack(eb1c, 0.f);
    }

#pragma unroll 4
    for (int k2 = 0; k2 < D / 2; k2++) {
        float2 w0 = g_vWT2 [k2 * D + c];
        float2 w1 = g_W1Ta2[k2 * D + c];
        float2 w2 = g_W1Tb2[k2 * D + c];
        ull w0u = *(ull*)&w0, w1u = *(ull*)&w1, w2u = *(ull*)&w2;
#pragma unroll
        for (int r = 0; r < STILE; r++) {
            ull nvp = *(const ull*)&nv[r][2 * k2];
            ull dsp = *(const ull*)&ds[r][2 * k2];
            accv2[r] = ffma2(nvp, w0u, accv2[r]);
            acca2[r] = ffma2(dsp, w1u, acca2[r]);
            accb2[r] = ffma2(dsp, w2u, accb2[r]);
        }
    }

    float accv[STILE], acca[STILE], accb[STILE];
#pragma unroll
    for (int r = 0; r < STILE; r++) {
        float lo, hi;
        funpack(accv2[r], lo, hi); accv[r] = lo + hi;
        funpack(acca2[r], lo, hi); acca[r] = lo + hi;
        funpack(accb2[r], lo, hi); accb[r] = lo + hi;
    }

    int lane = c & 31, w = c >> 5;
#pragma unroll
    for (int r = 0; r < STILE; r++) {
        int s = s0 + r;
        bool valid = (s < S);
        float a  = valid ? acca[r] : 0.f;
        float bb = valid ? accb[r] : 0.f;
        g_v   [(b * S1 + s) * D + c] = accv[r];
        g_A   [(b * S1 + s) * D + c] = a;
        g_Brow[(b * S1 + s) * D + c] = bb;
        g_Abf [(b * S1 + s) * D + c] = __float2bfloat16(a);
        g_Bbf [(b * S1 + s) * D + c] = __float2bfloat16(bb);
        ((float*)g_At2)[((b * 128 + (c >> 1)) * S1 + s) * 2 + (c & 1)] = a;
        ((float*)g_Bt2)[((b * 128 + (c >> 1)) * S1 + s) * 2 + (c & 1)] = bb;

        float4 v4 = make_float4(a, a * a, bb, bb * bb);
#pragma unroll
        for (int o = 16; o > 0; o >>= 1) {
            v4.x += __shfl_xor_sync(0xffffffffu, v4.x, o);
            v4.y += __shfl_xor_sync(0xffffffffu, v4.y, o);
            v4.z += __shfl_xor_sync(0xffffffffu, v4.z, o);
            v4.w += __shfl_xor_sync(0xffffffffu, v4.w, o);
        }
        if (lane == 0) wr[w] = v4;
        __syncthreads();
        if (c == 0) {
            float4 t = wr[0];
#pragma unroll
            for (int q = 1; q < 8; q++) {
                float4 o = wr[q];
                t.x += o.x; t.y += o.y; t.z += o.z; t.w += o.w;
            }
            g_SA[b * S1 + s] = t.x; g_QA[b * S1 + s] = t.y;
            g_SB[b * S1 + s] = t.z; g_QB[b * S1 + s] = t.w;
        }
        __syncthreads();
    }

    {
        float kacc[H];
#pragma unroll
        for (int h = 0; h < H; h++) kacc[h] = 0.f;
        for (int k = lane; k < D; k += 32) {
            float n = nv[w][k];
#pragma unroll
            for (int h = 0; h < H; h++) kacc[h] = fmaf(n, g_uk[h * D + k], kacc[h]);
        }
#pragma unroll
        for (int h = 0; h < H; h++) {
#pragma unroll
            for (int o = 16; o > 0; o >>= 1)
                kacc[h] += __shfl_xor_sync(0xffffffffu, kacc[h], o);
            if (lane == 0) g_ks[(b * H + h) * S1 + s0 + w] = kacc[h];
        }
    }
}

// ---------------- kernel 1b: G = A . B^T via wmma bf16 tensor cores ----------------
// block: 64 i x 64 j tile, full K=256 resident in smem; 8 warps as 2(i) x 4(j),
// each warp = 2 x (16x16) output frags.
__global__ void __launch_bounds__(256) k_gemmG() {
    int b  = blockIdx.z;
    int i0 = blockIdx.y * 64;
    int j0 = blockIdx.x * 64;
    __shared__ __nv_bfloat16 As[64][264];   // ld=264 elem (528B, odd 16B-units -> conflict-free ldmatrix)
    __shared__ __nv_bfloat16 Bs[64][264];
    int t = threadIdx.x;

    // load 64x256 bf16 tiles: thread -> row t>>2, 64 ch chunk (t&3)*64, 8 x 16B
    int lrow = t >> 2, lc = (t & 3) * 64;
    const uint4* asrc = (const uint4*)&g_Abf[((size_t)(b * S1 + i0 + lrow)) * D + lc];
    const uint4* bsrc = (const uint4*)&g_Bbf[((size_t)(b * S1 + j0 + lrow)) * D + lc];
#pragma unroll
    for (int q = 0; q < 8; q++) {
        *(uint4*)&As[lrow][lc + q * 8] = asrc[q];
        *(uint4*)&Bs[lrow][lc + q * 8] = bsrc[q];
    }
    __syncthreads();

    int w  = t >> 5;
    int wi = w & 1;        // i half: 32 rows
    int wj = w >> 1;       // j quarter: 16 cols

    wmma::fragment<wmma::accumulator, 16, 16, 16, float> dfrag[2];
#pragma unroll
    for (int m = 0; m < 2; m++) wmma::fill_fragment(dfrag[m], 0.0f);

    for (int kk = 0; kk < D; kk += 16) {
        wmma::fragment<wmma::matrix_a, 16, 16, 16, __nv_bfloat16, wmma::row_major> af;
        wmma::fragment<wmma::matrix_b, 16, 16, 16, __nv_bfloat16, wmma::col_major> bf;
        wmma::load_matrix_sync(bf, &Bs[wj * 16][kk], 264);
#pragma unroll
        for (int m = 0; m < 2; m++) {
            wmma::load_matrix_sync(af, &As[wi * 32 + m * 16][kk], 264);
            wmma::mma_sync(dfrag[m], af, bf, dfrag[m]);
        }
    }
#pragma unroll
    for (int m = 0; m < 2; m++) {
        wmma::store_matrix_sync(&g_G[((size_t)(b * S1 + i0 + wi * 32 + m * 16)) * S1 + j0 + wj * 16],
                                dfrag[m], S1, wmma::mem_row_major);
    }
}

// ---------------- kernel 2a: partial logits (channel-split) ----------------
template <bool CLS>
__device__ __forceinline__ void edge_loop(
    int base, const long long* __restrict__ btp, const long long* __restrict__ atp,
    const float (*As4)[D], const ull* gp2, const ull* bp2,
    const ulonglong2* V2u, const ull* rstd2, const ull* nmu2,
    ull acc01[ITILE], ull acc23[ITILE], ull acc45[ITILE], ull acc67[ITILE]) {
#pragma unroll 2
    for (int cc = 0; cc < 64; cc++) {
        int c2 = base + cc;
        ull bt2 = (ull)btp[c2 * S1];
        ull acls = 0;
        if (CLS) acls = (ull)atp[c2 * S1];
        ull g2 = gp2[c2], b2 = bp2[c2];
        ulonglong2 p0 = V2u[4 * c2 + 0], p1 = V2u[4 * c2 + 1];
        ulonglong2 p2 = V2u[4 * c2 + 2], p3 = V2u[4 * c2 + 3];
#pragma unroll
        for (int r = 0; r < ITILE; r++) {
            ull a2 = (CLS && r == 0) ? acls : *(const ull*)&As4[r][2 * c2];
            ull x2 = fadd2(a2, bt2);
            ull t2 = ffma2(x2, rstd2[r], nmu2[r]);
            ull y2 = ffma2(t2, g2, b2);
            float y0, y1; funpack(y2, y0, y1);
            y0 = fmaxf(y0, 0.f); y1 = fmaxf(y1, 0.f);
            ull yy0 = fpack(y0, y0), yy1 = fpack(y1, y1);
            acc01[r] = ffma2(yy0, p0.x, acc01[r]);
            acc23[r] = ffma2(yy0, p0.y, acc23[r]);
            acc45[r] = ffma2(yy0, p1.x, acc45[r]);
            acc67[r] = ffma2(yy0, p1.y, acc67[r]);
            acc01[r] = ffma2(yy1, p2.x, acc01[r]);
            acc23[r] = ffma2(yy1, p2.y, acc23[r]);
            acc45[r] = ffma2(yy1, p3.x, acc45[r]);
            acc67[r] = ffma2(yy1, p3.y, acc67[r]);
        }
    }
}

__global__ void __launch_bounds__(256) k_logits(
    const float* __restrict__ lng, const float* __restrict__ lnb) {
    int i0 = blockIdx.x * ITILE;
    int b  = blockIdx.y;
    int half = blockIdx.z;
    int t = threadIdx.x;
    bool hasCls = (i0 == 0);

    __shared__ float As4[ITILE][D];
    __shared__ ull gp2[D / 2];
    __shared__ ull bp2[D / 2];
    __shared__ ulonglong2 V2u[2 * D];

#pragma unroll
    for (int r = 0; r < ITILE; r++) {
        int i = i0 + r;
        As4[r][t] = (i > 0) ? g_A[(b * S1 + i - 1) * D + t] : 0.f;
    }
    if (t < 128) {
        gp2[t] = fpack(lng[2 * t], lng[2 * t + 1]);
        bp2[t] = fpack(lnb[2 * t], lnb[2 * t + 1]);
    }
    {
        const ulonglong2* src = (const ulonglong2*)g_V2;
        V2u[t] = src[t]; V2u[t + 256] = src[t + 256];
    }
    __syncthreads();

    int jn = (t > 0) ? t - 1 : 0;
    float sb = g_SB[b * S1 + jn], qb = g_QB[b * S1 + jn];
    ull rstd2[ITILE], nmu2[ITILE];
#pragma unroll
    for (int r = 0; r < ITILE; r++) {
        int i = i0 + r;
        float sa, qa, gij;
        if (i == 0) {
            sa = g_SA[b * S1 + jn]; qa = g_QA[b * S1 + jn];
            gij = g_G[(b * S1 + jn) * S1 + jn];
        } else {
            sa = g_SA[b * S1 + i - 1]; qa = g_QA[b * S1 + i - 1];
            gij = g_G[(b * S1 + i - 1) * S1 + jn];
        }
        const float invD = 1.0f / D;
        float m = (sa + sb) * invD;
        float var = fmaf(2.f, gij, qa + qb) * invD - m * m;
        float rs = rsqrtf(var + 1e-5f);
        rstd2[r] = fpack(rs, rs);
        float nm = -m * rs;
        nmu2[r] = fpack(nm, nm);
    }

    const long long* btp = (const long long*)g_Bt2 + (long long)(b * 128) * S1 + jn;
    const long long* atp = (const long long*)g_At2 + (long long)(b * 128) * S1 + jn;

    ull acc01[ITILE], acc23[ITILE], acc45[ITILE], acc67[ITILE];
    ull z = fpack(0.f, 0.f);
#pragma unroll
    for (int r = 0; r < ITILE; r++) { acc01[r] = z; acc23[r] = z; acc45[r] = z; acc67[r] = z; }

    int base = half * 64;
    if (hasCls) edge_loop<true >(base, btp, atp, As4, gp2, bp2, V2u, rstd2, nmu2, acc01, acc23, acc45, acc67);
    else        edge_loop<false>(base, btp, atp, As4, gp2, bp2, V2u, rstd2, nmu2, acc01, acc23, acc45, acc67);

    float* dst = half ? g_part1 : g_part0;
#pragma unroll
    for (int r = 0; r < ITILE; r++) {
        float l0, l1, l2, l3, l4, l5, l6, l7;
        funpack(acc01[r], l0, l1); funpack(acc23[r], l2, l3);
        funpack(acc45[r], l4, l5); funpack(acc67[r], l6, l7);
        float hv[H] = {l0, l1, l2, l3, l4, l5, l6, l7};
        float* pp = dst + ((b * S1 + i0 + r) * H) * S1 + t;
#pragma unroll
        for (int h = 0; h < H; h++) pp[h * S1] = hv[h];
    }
}

// ---------------- kernel 2b: softmax + context (float4 j-split ctx, combined) ----------------
__global__ void __launch_bounds__(256) k_smax(float* __restrict__ out) {
    int b = blockIdx.x >> 8, i = blockIdx.x & 255;
    int t = threadIdx.x;
    __shared__ float attn_s[H][S1 + 8];
    __shared__ float red[H];
    __shared__ float4 part4[4][64];

    const float* p0 = g_part0 + ((b * S1 + i) * H) * S1 + t;
    const float* p1 = g_part1 + ((b * S1 + i) * H) * S1 + t;
    const float* ksp = g_ks + b * H * S1 + t;

    float lg[H];
#pragma unroll
    for (int h = 0; h < H; h++) {
        lg[h] = (t > 0) ? p0[h * S1] + p1[h * S1] + ksp[h * S1] : -1e30f;
        attn_s[h][t] = lg[h];
    }
    __syncthreads();

    int w = t >> 5, l = t & 31;
    float m = -1e30f;
#pragma unroll
    for (int k = 0; k < 8; k++) m = fmaxf(m, attn_s[w][l + 32 * k]);
#pragma unroll
    for (int o = 16; o > 0; o >>= 1) m = fmaxf(m, __shfl_xor_sync(0xffffffffu, m, o));
    if (l == 0) red[w] = m;
    __syncthreads();

    float p[H];
#pragma unroll
    for (int h = 0; h < H; h++) {
        p[h] = (t > 0) ? __expf(lg[h] - red[h]) : 0.f;
        attn_s[h][t] = p[h];
    }
    __syncthreads();

    float sm = 0.f;
#pragma unroll
    for (int k = 0; k < 8; k++) sm += attn_s[w][l + 32 * k];
#pragma unroll
    for (int o = 16; o > 0; o >>= 1) sm += __shfl_xor_sync(0xffffffffu, sm, o);
    if (l == 0) red[w] = 1.0f / sm;
    __syncthreads();

    float* arow = out + AOFF + ((b * H) * S1 + i) * S1 + t;
#pragma unroll
    for (int h = 0; h < H; h++) {
        float a = p[h] * red[h];
        attn_s[h][t] = a;
        arow[h * S1 * S1] = a;
    }
    __syncthreads();

    // ctx: thread (jg, cg): 4 channels (float4), 64 j's; reduce 4 partials
    int jg = t >> 6, cg = t & 63, hh = cg >> 3;
    const float4* vp4 = (const float4*)(g_v + (size_t)b * S1 * D) + cg;
    float4 a4 = make_float4(0.f, 0.f, 0.f, 0.f);
    int jbeg = jg * 64;
#pragma unroll 4
    for (int j = jbeg; j < jbeg + 64; j++) {
        float wgt = attn_s[hh][j];
        float4 v4 = vp4[(size_t)j * 64];
        a4.x = fmaf(wgt, v4.x, a4.x);
        a4.y = fmaf(wgt, v4.y, a4.y);
        a4.z = fmaf(wgt, v4.z, a4.z);
        a4.w = fmaf(wgt, v4.w, a4.w);
    }
    part4[jg][cg] = a4;
    __syncthreads();
    if (t < 64) {
        float4 r0 = part4[0][t], r1 = part4[1][t], r2 = part4[2][t], r3 = part4[3][t];
        r0.x += r1.x + r2.x + r3.x;
        r0.y += r1.y + r2.y + r3.y;
        r0.z += r1.z + r2.z + r3.z;
        r0.w += r1.w + r2.w + r3.w;
        ((float4*)(out + ((size_t)(b * S1) + i) * D))[t] = r0;
    }
}

// ---------------- launch ----------------
extern "C" void kernel_launch(void* const* d_in, const int* in_sizes, int n_in,
                              void* d_out, int out_size) {
    (void)in_sizes; (void)n_in; (void)out_size;
    const float* desc = (const float*)d_in[0];
    const float* nve  = (const float*)d_in[1];
    const float* kW   = (const float*)d_in[4];
    const float* vW   = (const float*)d_in[6];
    const float* vb   = (const float*)d_in[7];
    const float* eW1  = (const float*)d_in[8];
    const float* eb1  = (const float*)d_in[9];
    const float* lng  = (const float*)d_in[10];
    const float* lnb  = (const float*)d_in[11];
    const float* eW2  = (const float*)d_in[12];
    const float* aW   = (const float*)d_in[14];
    float* out = (float*)d_out;

    k_transpose<<<dim3(4, 8, 3), 256>>>(vW, eW1);
    k_wvec<<<H, 256>>>(kW, eW2, aW);
    k_node<<<B * 32, 256>>>(desc, nve, vb, eb1);
    k_gemmG<<<dim3(4, 4, B), 256>>>();
    k_logits<<<dim3(S1 / ITILE, B, 2), 256>>>(lng, lnb);
    k_smax<<<B * S1, 256>>>(out);
}